// round 1
// baseline (speedup 1.0000x reference)
#include <cuda_runtime.h>
#include <stdint.h>
#include <math.h>

// ---------------- problem constants ----------------
#define BN 128          // batch
#define PN 512          // points
#define SI 128          // ITER_SAMPLES
#define NI 4            // NUM_ITER

// output layout (tuple flattened in order), float32
#define OFF_POSE_OPT 0                    // (B,4)   512
#define OFF_COST     512                  // (B)     128
#define OFF_PLUS     640                  // (B,4)   512
#define OFF_SAMP     1152                 // (512,B,4) 262144
#define OFF_LW       263296               // (512,B) 65536
#define OFF_CINIT    328832               // (B)     128

// JAX PRNG variant switches (flip if rel_err is large):
//   JAX_PARTITIONABLE: 1 = new default (>=0.4.36) fold-like split + 64-bit counter bits
//   JAX_XOR_FOLD: for partitionable 32-bit bits: 1 = bits1^bits2, 0 = bits1
#define JAX_PARTITIONABLE 1
#define JAX_XOR_FOLD 1

// ---------------- device scratch ----------------
__device__ float g_C[NI * SI * BN];
__device__ float g_TM[NI][BN][3];
__device__ float g_TS[NI][BN][3];
__device__ float g_RM[NI][BN];
__device__ float g_RS[NI][BN];

// ---------------- threefry2x32 (JAX) ----------------
__host__ __device__ __forceinline__ void tf2x32(uint32_t k0, uint32_t k1,
                                                uint32_t& x0, uint32_t& x1) {
    uint32_t ks2 = k0 ^ k1 ^ 0x1BD11BDAu;
    x0 += k0; x1 += k1;
#define TFR(r) { x0 += x1; x1 = (x1 << (r)) | (x1 >> (32 - (r))); x1 ^= x0; }
    TFR(13) TFR(15) TFR(26) TFR(6)   x0 += k1;  x1 += ks2 + 1u;
    TFR(17) TFR(29) TFR(16) TFR(24)  x0 += ks2; x1 += k0 + 2u;
    TFR(13) TFR(15) TFR(26) TFR(6)   x0 += k0;  x1 += k1 + 3u;
    TFR(17) TFR(29) TFR(16) TFR(24)  x0 += k1;  x1 += ks2 + 4u;
    TFR(13) TFR(15) TFR(26) TFR(6)   x0 += ks2; x1 += k0 + 5u;
#undef TFR
}

// XLA ErfInv32 (Giles polynomial), exactly as in xla/client/lib/math.cc
__device__ __forceinline__ float xla_erfinv(float x) {
    float w = -log1pf(-x * x);
    float p;
    if (w < 5.0f) {
        w = w - 2.5f;
        p = 2.81022636e-08f;
        p = fmaf(p, w, 3.43273939e-07f);
        p = fmaf(p, w, -3.5233877e-06f);
        p = fmaf(p, w, -4.39150654e-06f);
        p = fmaf(p, w, 0.00021858087f);
        p = fmaf(p, w, -0.00125372503f);
        p = fmaf(p, w, -0.00417768164f);
        p = fmaf(p, w, 0.246640727f);
        p = fmaf(p, w, 1.50140941f);
    } else {
        w = sqrtf(w) - 3.0f;
        p = -0.000200214257f;
        p = fmaf(p, w, 0.000100950558f);
        p = fmaf(p, w, 0.00134934322f);
        p = fmaf(p, w, -0.00367342844f);
        p = fmaf(p, w, 0.00573950773f);
        p = fmaf(p, w, -0.0076224613f);
        p = fmaf(p, w, 0.00943887047f);
        p = fmaf(p, w, 1.00167406f);
        p = fmaf(p, w, 2.83297682f);
    }
    return p * x;
}

// jax.random.normal: uniform in [-1+2^-24, 1) then sqrt(2)*erfinv
__device__ __forceinline__ float bits_to_normal(uint32_t bits) {
    float f = __uint_as_float((bits >> 9) | 0x3f800000u) - 1.0f;  // [0,1)
    const float lo = -0.99999994f;                                 // nextafter(-1,0)
    float u = fmaf(f, 2.0f, lo);                                   // (hi-lo)==2.0f exactly
    u = fmaxf(u, lo);
    return 1.41421356237f * xla_erfinv(u);
}

// ---------------- kernels ----------------

__global__ void init_kernel(const float* __restrict__ pose_init, float* __restrict__ out) {
    int b = blockIdx.x * blockDim.x + threadIdx.x;
    if (b >= BN) return;
    float4 p = reinterpret_cast<const float4*>(pose_init)[b];
    reinterpret_cast<float4*>(out + OFF_POSE_OPT)[b] = p;
    reinterpret_cast<float4*>(out + OFF_PLUS)[b] = p;
    g_TM[0][b][0] = p.x; g_TM[0][b][1] = p.y; g_TM[0][b][2] = p.z;
    g_TS[0][b][0] = 0.1f; g_TS[0][b][1] = 0.1f; g_TS[0][b][2] = 0.1f;
    g_RM[0][b] = p.w;
    g_RS[0][b] = 0.2f;
}

__global__ void cost_init_kernel(const float* __restrict__ pose,
                                 const float* __restrict__ x3d,
                                 const float* __restrict__ x2d,
                                 const float* __restrict__ w2d,
                                 const float* __restrict__ cam,
                                 float* __restrict__ out) {
    int b = blockIdx.x, t = threadIdx.x;
    __shared__ float red[256];
    float tx = pose[b * 4 + 0], ty = pose[b * 4 + 1], tz = pose[b * 4 + 2], yaw = pose[b * 4 + 3];
    float c = (float)cos((double)yaw), s = (float)sin((double)yaw);
    float fx = cam[b * 4 + 0], fy = cam[b * 4 + 1], cx = cam[b * 4 + 2], cy = cam[b * 4 + 3];
    float acc = 0.f;
    for (int p = t; p < PN; p += 256) {
        int base = b * PN + p;
        float X = x3d[base * 3 + 0], Y = x3d[base * 3 + 1], Z = x3d[base * 3 + 2];
        float Xc = fmaf(c, X, fmaf(s, Z, tx));
        float Yc = Y + ty;
        float Zc = fmaxf(fmaf(-s, X, fmaf(c, Z, tz)), 1e-5f);
        float inv = 1.0f / Zc;
        float u = fmaf(fx * Xc, inv, cx);
        float v = fmaf(fy * Yc, inv, cy);
        float ru = (u - x2d[base * 2 + 0]) * w2d[base * 2 + 0];
        float rv = (v - x2d[base * 2 + 1]) * w2d[base * 2 + 1];
        acc = fmaf(ru, ru, fmaf(rv, rv, acc));
    }
    red[t] = acc; __syncthreads();
    for (int o = 128; o; o >>= 1) { if (t < o) red[t] += red[t + o]; __syncthreads(); }
    if (t == 0) { float v = 0.5f * red[0]; out[OFF_COST + b] = v; out[OFF_CINIT + b] = v; }
}

// sample generation: writes samples for iteration `iter` directly into output region
__global__ void gen_kernel(int iter, uint32_t k1a, uint32_t k1b, uint32_t k2a, uint32_t k2b,
                           float* __restrict__ samp) {
    int tid = blockIdx.x * blockDim.x + threadIdx.x;
    float* dst = samp + (size_t)iter * SI * BN * 4;
#if JAX_PARTITIONABLE
    // per-element 64-bit counter (hi=0, lo=index); bits = out0 (^ out1 if fold)
    const int NT = SI * BN * 3;   // 49152 trans elements
    const int NR = SI * BN;       // 16384 rot elements
    if (tid < NT) {
        uint32_t x0 = 0u, x1 = (uint32_t)tid;
        tf2x32(k1a, k1b, x0, x1);
#if JAX_XOR_FOLD
        uint32_t bits = x0 ^ x1;
#else
        uint32_t bits = x0;
#endif
        float n = bits_to_normal(bits);
        int d = tid % 3; int sb = tid / 3; int b = sb % BN; int s = sb / BN;
        dst[(s * BN + b) * 4 + d] = fmaf(g_TS[iter][b][d], n, g_TM[iter][b][d]);
    } else if (tid < NT + NR) {
        int e = tid - NT;
        uint32_t x0 = 0u, x1 = (uint32_t)e;
        tf2x32(k2a, k2b, x0, x1);
#if JAX_XOR_FOLD
        uint32_t bits = x0 ^ x1;
#else
        uint32_t bits = x0;
#endif
        float n = bits_to_normal(bits);
        int b = e % BN; int s = e / BN;
        dst[(s * BN + b) * 4 + 3] = fmaf(g_RS[iter][b], n, g_RM[iter][b]);
    }
#else
    // legacy threefry: counts iota32 split in halves; pair (i, i+n/2) -> (out0_i, out1_i)
    const int HT = SI * BN * 3 / 2;   // 24576 trans pairs
    const int HR = SI * BN / 2;       // 8192 rot pairs
    if (tid < HT) {
        uint32_t x0 = (uint32_t)tid, x1 = (uint32_t)(tid + HT);
        tf2x32(k1a, k1b, x0, x1);
        uint32_t xs[2] = { x0, x1 };
#pragma unroll
        for (int h = 0; h < 2; h++) {
            int e = tid + h * HT;
            float n = bits_to_normal(xs[h]);
            int d = e % 3; int sb = e / 3; int b = sb % BN; int s = sb / BN;
            dst[(s * BN + b) * 4 + d] = fmaf(g_TS[iter][b][d], n, g_TM[iter][b][d]);
        }
    } else if (tid < HT + HR) {
        int j = tid - HT;
        uint32_t x0 = (uint32_t)j, x1 = (uint32_t)(j + HR);
        tf2x32(k2a, k2b, x0, x1);
        uint32_t xs[2] = { x0, x1 };
#pragma unroll
        for (int h = 0; h < 2; h++) {
            int e = j + h * HR;
            float n = bits_to_normal(xs[h]);
            int b = e % BN; int s = e / BN;
            dst[(s * BN + b) * 4 + 3] = fmaf(g_RS[iter][b], n, g_RM[iter][b]);
        }
    }
#endif
}

// cost of 128 sample-poses for one b per block; 512 threads = 128 samples x 4 point-quarters
__global__ void cost_kernel(const float* __restrict__ poses, int iter,
                            const float* __restrict__ x3d,
                            const float* __restrict__ x2d,
                            const float* __restrict__ w2d,
                            const float* __restrict__ cam) {
    __shared__ float4 sA[PN];   // X,Y,Z,wu
    __shared__ float4 sB[PN];   // u2,v2,wv,0
    __shared__ float red[512];
    const int b = blockIdx.x, t = threadIdx.x;
    for (int p = t; p < PN; p += 512) {
        int base = b * PN + p;
        sA[p] = make_float4(x3d[base * 3 + 0], x3d[base * 3 + 1], x3d[base * 3 + 2],
                            w2d[base * 2 + 0]);
        sB[p] = make_float4(x2d[base * 2 + 0], x2d[base * 2 + 1], w2d[base * 2 + 1], 0.f);
    }
    __syncthreads();
    const int s = t & (SI - 1), q = t >> 7;
    float4 pp = reinterpret_cast<const float4*>(poses)[s * BN + b];
    float c = (float)cos((double)pp.w), sn = (float)sin((double)pp.w);
    float fx = cam[b * 4 + 0], fy = cam[b * 4 + 1], cx = cam[b * 4 + 2], cy = cam[b * 4 + 3];
    float acc = 0.f;
    const int p0 = q * (PN / 4);
#pragma unroll 4
    for (int p = p0; p < p0 + PN / 4; p++) {
        float4 A = sA[p]; float4 Bv = sB[p];
        float Xc = fmaf(c, A.x, fmaf(sn, A.z, pp.x));
        float Yc = A.y + pp.y;
        float Zc = fmaxf(fmaf(-sn, A.x, fmaf(c, A.z, pp.z)), 1e-5f);
        float inv = 1.0f / Zc;
        float u = fmaf(fx * Xc, inv, cx);
        float v = fmaf(fy * Yc, inv, cy);
        float ru = (u - Bv.x) * A.w;
        float rv = (v - Bv.y) * Bv.z;
        acc = fmaf(ru, ru, fmaf(rv, rv, acc));
    }
    red[t] = acc; __syncthreads();
    if (q == 0) {
        float tot = (red[s] + red[s + 128]) + (red[s + 256] + red[s + 384]);
        g_C[(iter * SI + s) * BN + b] = 0.5f * tot;
    }
}

// logweights for all samples so far (mixture of IT+1 proposals) + param update
template <int IT>
__global__ void lw_kernel(const float* __restrict__ samp, float* __restrict__ out_lw) {
    const int b = blockIdx.x, t = threadIdx.x;   // 256 threads
    const int M = (IT + 1) * SI;
    __shared__ float slw[NI * SI];
    __shared__ float4 sp[NI * SI];
    __shared__ float red[256];

    float tmv[IT + 1][3], tsv[IT + 1][3], rmv[IT + 1], rsv[IT + 1], cq[IT + 1];
#pragma unroll
    for (int q = 0; q <= IT; q++) {
        float l = 0.f;
#pragma unroll
        for (int d = 0; d < 3; d++) {
            tmv[q][d] = g_TM[q][b][d];
            tsv[q][d] = g_TS[q][b][d];
            l += logf(tsv[q][d]);
        }
        rmv[q] = g_RM[q][b]; rsv[q] = g_RS[q][b];
        cq[q] = -(l + logf(rsv[q])) - 2.0f * 1.8378770664093453f;  // -1.5*log2pi - 0.5*log2pi
    }
    const float4* sptr = reinterpret_cast<const float4*>(samp);
    for (int m = t; m < M; m += 256) {
        float4 p = sptr[m * BN + b];
        sp[m] = p;
        float mx = -1e30f;
        float lp[IT + 1];
#pragma unroll
        for (int q = 0; q <= IT; q++) {
            float d0 = (p.x - tmv[q][0]) / tsv[q][0];
            float d1 = (p.y - tmv[q][1]) / tsv[q][1];
            float d2 = (p.z - tmv[q][2]) / tsv[q][2];
            float dr = (p.w - rmv[q]) / rsv[q];
            float v = fmaf(-0.5f, fmaf(d0, d0, fmaf(d1, d1, fmaf(d2, d2, dr * dr))), cq[q]);
            lp[q] = v; mx = fmaxf(mx, v);
        }
        float se = 0.f;
#pragma unroll
        for (int q = 0; q <= IT; q++) se += expf(lp[q] - mx);
        float mlp = mx + logf(se) - logf((float)(IT + 1));
        float lw = -g_C[m * BN + b] - mlp;
        slw[m] = lw;
        if constexpr (IT == NI - 1) out_lw[m * BN + b] = lw;
    }
    __syncthreads();
    if constexpr (IT < NI - 1) {
        // softmax over M samples, then weighted mean/std -> params[IT+1]
        float lmax = -1e30f;
        for (int m = t; m < M; m += 256) lmax = fmaxf(lmax, slw[m]);
        red[t] = lmax; __syncthreads();
        for (int o = 128; o; o >>= 1) { if (t < o) red[t] = fmaxf(red[t], red[t + o]); __syncthreads(); }
        lmax = red[0]; __syncthreads();

        float se = 0, s0 = 0, s1 = 0, s2 = 0, s3 = 0;
        for (int m = t; m < M; m += 256) {
            float e = expf(slw[m] - lmax); slw[m] = e;
            float4 p = sp[m];
            se += e;
            s0 = fmaf(e, p.x, s0); s1 = fmaf(e, p.y, s1);
            s2 = fmaf(e, p.z, s2); s3 = fmaf(e, p.w, s3);
        }
        auto bsum = [&](float v) -> float {
            red[t] = v; __syncthreads();
            for (int o = 128; o; o >>= 1) { if (t < o) red[t] += red[t + o]; __syncthreads(); }
            float r = red[0]; __syncthreads(); return r;
        };
        se = bsum(se); s0 = bsum(s0); s1 = bsum(s1); s2 = bsum(s2); s3 = bsum(s3);
        float inv = 1.0f / se;
        float m0 = s0 * inv, m1 = s1 * inv, m2 = s2 * inv, m3 = s3 * inv;
        float v0 = 0, v1 = 0, v2 = 0, v3 = 0;
        for (int m = t; m < M; m += 256) {
            float e = slw[m]; float4 p = sp[m];
            float d;
            d = p.x - m0; v0 = fmaf(e * d, d, v0);
            d = p.y - m1; v1 = fmaf(e * d, d, v1);
            d = p.z - m2; v2 = fmaf(e * d, d, v2);
            d = p.w - m3; v3 = fmaf(e * d, d, v3);
        }
        v0 = bsum(v0); v1 = bsum(v1); v2 = bsum(v2); v3 = bsum(v3);
        if (t == 0) {
            g_TM[IT + 1][b][0] = m0; g_TM[IT + 1][b][1] = m1; g_TM[IT + 1][b][2] = m2;
            g_TS[IT + 1][b][0] = sqrtf(fmaf(v0, inv, 1e-5f));
            g_TS[IT + 1][b][1] = sqrtf(fmaf(v1, inv, 1e-5f));
            g_TS[IT + 1][b][2] = sqrtf(fmaf(v2, inv, 1e-5f));
            g_RM[IT + 1][b] = m3;
            g_RS[IT + 1][b] = sqrtf(fmaf(v3, inv, 1e-5f));
        }
    }
}

// ---------------- host ----------------
extern "C" void kernel_launch(void* const* d_in, const int* in_sizes, int n_in,
                              void* d_out, int out_size) {
    const float* x3d = (const float*)d_in[0];
    const float* x2d = (const float*)d_in[1];
    const float* w2d = (const float*)d_in[2];
    const float* cam = (const float*)d_in[3];
    const float* pose_init = (const float*)d_in[4];
    float* out = (float*)d_out;

    // key chain: key = jax.random.key(42); per iter: key,k1,k2 = split(key,3)
    uint32_t K0 = 0u, K1 = 42u;
    uint32_t k1a[NI], k1b[NI], k2a[NI], k2b[NI];
    for (int i = 0; i < NI; i++) {
#if JAX_PARTITIONABLE
        uint32_t r[3][2];
        for (int j = 0; j < 3; j++) {
            uint32_t x0 = 0u, x1 = (uint32_t)j;
            tf2x32(K0, K1, x0, x1);
            r[j][0] = x0; r[j][1] = x1;
        }
        k1a[i] = r[1][0]; k1b[i] = r[1][1];
        k2a[i] = r[2][0]; k2b[i] = r[2][1];
        K0 = r[0][0]; K1 = r[0][1];
#else
        uint32_t a[3], bb[3];
        for (int j = 0; j < 3; j++) {
            uint32_t x0 = (uint32_t)j, x1 = (uint32_t)(j + 3);
            tf2x32(K0, K1, x0, x1);
            a[j] = x0; bb[j] = x1;
        }
        // out = [a0,a1,a2,b0,b1,b2].reshape(3,2)
        k1a[i] = a[2];  k1b[i] = bb[0];
        k2a[i] = bb[1]; k2b[i] = bb[2];
        K0 = a[0]; K1 = a[1];
#endif
    }

    init_kernel<<<1, 128>>>(pose_init, out);
    cost_init_kernel<<<BN, 256>>>(pose_init, x3d, x2d, w2d, cam, out);
    float* samp = out + OFF_SAMP;
    for (int i = 0; i < NI; i++) {
        gen_kernel<<<256, 256>>>(i, k1a[i], k1b[i], k2a[i], k2b[i], samp);
        cost_kernel<<<BN, 512>>>(samp + (size_t)i * SI * BN * 4, i, x3d, x2d, w2d, cam);
        switch (i) {
            case 0: lw_kernel<0><<<BN, 256>>>(samp, nullptr); break;
            case 1: lw_kernel<1><<<BN, 256>>>(samp, nullptr); break;
            case 2: lw_kernel<2><<<BN, 256>>>(samp, nullptr); break;
            case 3: lw_kernel<3><<<BN, 256>>>(samp, out + OFF_LW); break;
        }
    }
}

// round 2
// speedup vs baseline: 2.4543x; 2.4543x over previous
#include <cuda_runtime.h>
#include <stdint.h>
#include <math.h>

// ---------------- problem constants ----------------
#define BN 128          // batch
#define PN 512          // points
#define SI 128          // ITER_SAMPLES
#define NI 4            // NUM_ITER
#define LOG2PI 1.8378770664093453f

// output layout (tuple flattened in order), float32
#define OFF_POSE_OPT 0                    // (B,4)   512
#define OFF_COST     512                  // (B)     128
#define OFF_PLUS     640                  // (B,4)   512
#define OFF_SAMP     1152                 // (512,B,4) 262144
#define OFF_LW       263296               // (512,B) 65536
#define OFF_CINIT    328832               // (B)     128

typedef unsigned long long ull;

struct Keys {
    uint32_t a1[NI], b1[NI], a2[NI], b2[NI];
};

// ---------------- threefry2x32 (JAX, partitionable) ----------------
__host__ __device__ __forceinline__ void tf2x32(uint32_t k0, uint32_t k1,
                                                uint32_t& x0, uint32_t& x1) {
    uint32_t ks2 = k0 ^ k1 ^ 0x1BD11BDAu;
    x0 += k0; x1 += k1;
#define TFR(r) { x0 += x1; x1 = (x1 << (r)) | (x1 >> (32 - (r))); x1 ^= x0; }
    TFR(13) TFR(15) TFR(26) TFR(6)   x0 += k1;  x1 += ks2 + 1u;
    TFR(17) TFR(29) TFR(16) TFR(24)  x0 += ks2; x1 += k0 + 2u;
    TFR(13) TFR(15) TFR(26) TFR(6)   x0 += k0;  x1 += k1 + 3u;
    TFR(17) TFR(29) TFR(16) TFR(24)  x0 += k1;  x1 += ks2 + 4u;
    TFR(13) TFR(15) TFR(26) TFR(6)   x0 += ks2; x1 += k0 + 5u;
#undef TFR
}

// XLA ErfInv32 (Giles polynomial)
__device__ __forceinline__ float xla_erfinv(float x) {
    float w = -log1pf(-x * x);
    float p;
    if (w < 5.0f) {
        w = w - 2.5f;
        p = 2.81022636e-08f;
        p = fmaf(p, w, 3.43273939e-07f);
        p = fmaf(p, w, -3.5233877e-06f);
        p = fmaf(p, w, -4.39150654e-06f);
        p = fmaf(p, w, 0.00021858087f);
        p = fmaf(p, w, -0.00125372503f);
        p = fmaf(p, w, -0.00417768164f);
        p = fmaf(p, w, 0.246640727f);
        p = fmaf(p, w, 1.50140941f);
    } else {
        w = sqrtf(w) - 3.0f;
        p = -0.000200214257f;
        p = fmaf(p, w, 0.000100950558f);
        p = fmaf(p, w, 0.00134934322f);
        p = fmaf(p, w, -0.00367342844f);
        p = fmaf(p, w, 0.00573950773f);
        p = fmaf(p, w, -0.0076224613f);
        p = fmaf(p, w, 0.00943887047f);
        p = fmaf(p, w, 1.00167406f);
        p = fmaf(p, w, 2.83297682f);
    }
    return p * x;
}

__device__ __forceinline__ float bits_to_normal(uint32_t bits) {
    float f = __uint_as_float((bits >> 9) | 0x3f800000u) - 1.0f;  // [0,1)
    const float lo = -0.99999994f;                                 // nextafter(-1,0)
    float u = fmaf(f, 2.0f, lo);
    u = fmaxf(u, lo);
    return 1.41421356237f * xla_erfinv(u);
}

// ---------------- packed f32x2 helpers (sm_100+) ----------------
__device__ __forceinline__ ull pk2(float lo, float hi) {
    ull r; asm("mov.b64 %0, {%1, %2};" : "=l"(r) : "f"(lo), "f"(hi)); return r;
}
__device__ __forceinline__ void upk2(ull v, float& lo, float& hi) {
    asm("mov.b64 {%0, %1}, %2;" : "=f"(lo), "=f"(hi) : "l"(v));
}
__device__ __forceinline__ ull fma2(ull a, ull b, ull c) {
    ull d; asm("fma.rn.f32x2 %0, %1, %2, %3;" : "=l"(d) : "l"(a), "l"(b), "l"(c)); return d;
}
__device__ __forceinline__ ull mul2(ull a, ull b) {
    ull d; asm("mul.rn.f32x2 %0, %1, %2;" : "=l"(d) : "l"(a), "l"(b)); return d;
}
__device__ __forceinline__ float rcpa(float x) {
    float r; asm("rcp.approx.f32 %0, %1;" : "=f"(r) : "f"(x)); return r;
}

// one packed point-pair cost step
__device__ __forceinline__ ull pair_step(const ulonglong2* __restrict__ pv,
                                         ull cs2, ull sn2, ull nsn2,
                                         ull tx2, ull ty2, ull tz2, ull acc2) {
    ulonglong2 m0 = pv[0];   // X2, Z2
    ulonglong2 m1 = pv[1];   // A2, B2
    ulonglong2 m2 = pv[2];   // C2, E2
    ulonglong2 m3 = pv[3];   // D2, pad
    ull Xc2 = fma2(cs2, m0.x, fma2(sn2, m0.y, tx2));
    ull Zc2 = fma2(nsn2, m0.x, fma2(cs2, m0.y, tz2));
    float zl, zh; upk2(Zc2, zl, zh);
    float il = rcpa(fmaxf(zl, 1e-5f));
    float ih = rcpa(fmaxf(zh, 1e-5f));
    ull inv2 = pk2(il, ih);
    ull ru2 = fma2(mul2(m1.x, Xc2), inv2, m1.y);
    ull rv2 = fma2(fma2(m2.x, ty2, m2.y), inv2, m3.x);
    acc2 = fma2(ru2, ru2, acc2);
    acc2 = fma2(rv2, rv2, acc2);
    return acc2;
}

// ---------------- block reductions (512 thr = 16 warps) ----------------
template <int K>
__device__ __forceinline__ void block_sum(float* v, float* scr, int t) {
    int lane = t & 31, w = t >> 5;
#pragma unroll
    for (int k = 0; k < K; k++) {
        float x = v[k];
#pragma unroll
        for (int o = 16; o; o >>= 1) x += __shfl_xor_sync(0xffffffffu, x, o);
        if (lane == 0) scr[k * 16 + w] = x;
    }
    __syncthreads();
    if (t < K) {
        float s = 0.f;
#pragma unroll
        for (int w2 = 0; w2 < 16; w2++) s += scr[t * 16 + w2];
        scr[16 * K + t] = s;
    }
    __syncthreads();
#pragma unroll
    for (int k = 0; k < K; k++) v[k] = scr[16 * K + k];
}

__device__ __forceinline__ float block_max(float x, float* scr, int t) {
    int lane = t & 31, w = t >> 5;
#pragma unroll
    for (int o = 16; o; o >>= 1) x = fmaxf(x, __shfl_xor_sync(0xffffffffu, x, o));
    if (lane == 0) scr[w] = x;
    __syncthreads();
    if (t == 0) {
        float s = scr[0];
#pragma unroll
        for (int w2 = 1; w2 < 16; w2++) s = fmaxf(s, scr[w2]);
        scr[16] = s;
    }
    __syncthreads();
    return scr[16];
}

// ---------------- fused AMIS kernel: one block per batch element ----------------
__global__ __launch_bounds__(512, 1)
void amis_kernel(const float* __restrict__ x3d, const float* __restrict__ x2d,
                 const float* __restrict__ w2d, const float* __restrict__ cam,
                 const float* __restrict__ pose_init, float* __restrict__ out,
                 Keys keys) {
    __shared__ __align__(16) float s_pts[256 * 16];  // 256 pairs x {X2,Z2,A2,B2,C2,E2,D2,pad}
    __shared__ float s_pose[4 * 512];                 // SoA: dim*512 + m
    __shared__ float s_cs[SI], s_sn[SI];
    __shared__ float s_cost[512];
    __shared__ float red[512];
    __shared__ float s_scr[96];
    __shared__ float s_tm[NI][3], s_ts[NI][3], s_its[NI][3];
    __shared__ float s_rm[NI], s_rs[NI], s_irs[NI], s_cq[NI];

    const int b = blockIdx.x, t = threadIdx.x;

    const float fx = cam[b * 4 + 0], fy = cam[b * 4 + 1];
    const float cx = cam[b * 4 + 2], cy = cam[b * 4 + 3];
    const float4 pinit = reinterpret_cast<const float4*>(pose_init)[b];

    // ---- point preprocessing: fold camera+weights into per-point constants ----
    {
        int p = t;  // PN == 512 == blockDim
        int base = b * PN + p;
        float X = x3d[base * 3 + 0], Y = x3d[base * 3 + 1], Z = x3d[base * 3 + 2];
        float u2 = x2d[base * 2 + 0], v2 = x2d[base * 2 + 1];
        float wu = w2d[base * 2 + 0], wv = w2d[base * 2 + 1];
        float A = wu * fx, B = wu * (cx - u2);
        float C = wv * fy, E = C * Y, D = wv * (cy - v2);
        int o = (p >> 1) * 16 + (p & 1);
        s_pts[o + 0] = X;  s_pts[o + 2] = Z;
        s_pts[o + 4] = A;  s_pts[o + 6] = B;
        s_pts[o + 8] = C;  s_pts[o + 10] = E;
        s_pts[o + 12] = D; s_pts[o + 14] = 0.f;
    }
    if (t == 0) {
        s_tm[0][0] = pinit.x; s_tm[0][1] = pinit.y; s_tm[0][2] = pinit.z;
        s_ts[0][0] = 0.1f; s_ts[0][1] = 0.1f; s_ts[0][2] = 0.1f;
        s_its[0][0] = 10.f; s_its[0][1] = 10.f; s_its[0][2] = 10.f;
        s_rm[0] = pinit.w; s_rs[0] = 0.2f; s_irs[0] = 5.f;
        s_cq[0] = -(3.f * logf(0.1f) + logf(0.2f)) - 2.f * LOG2PI;
        reinterpret_cast<float4*>(out + OFF_POSE_OPT)[b] = pinit;
        reinterpret_cast<float4*>(out + OFF_PLUS)[b] = pinit;
    }
    __syncthreads();

    // ---- cost_init ----
    {
        float snI, csI;
        sincosf(pinit.w, &snI, &csI);
        float accv = 0.f;
        if (t < 256) {
            ull cs2 = pk2(csI, csI), sn2 = pk2(snI, snI), nsn2 = pk2(-snI, -snI);
            ull tx2 = pk2(pinit.x, pinit.x), ty2 = pk2(pinit.y, pinit.y), tz2 = pk2(pinit.z, pinit.z);
            const ulonglong2* pv = reinterpret_cast<const ulonglong2*>(s_pts) + t * 4;
            ull acc2 = pair_step(pv, cs2, sn2, nsn2, tx2, ty2, tz2, 0ull);
            float al, ah; upk2(acc2, al, ah);
            accv = al + ah;
        }
        block_sum<1>(&accv, s_scr, t);
        if (t == 0) {
            float v = 0.5f * accv;
            out[OFF_COST + b] = v;
            out[OFF_CINIT + b] = v;
        }
    }

    // ---- AMIS iterations ----
    for (int i = 0; i < NI; i++) {
        const int M0 = i * SI;
        // gen: one random element per thread (384 trans + 128 rot)
        if (t < 384) {
            int s = t / 3, d = t - s * 3;
            uint32_t x0 = 0u, x1 = (uint32_t)((s * BN + b) * 3 + d);
            tf2x32(keys.a1[i], keys.b1[i], x0, x1);
            float n = bits_to_normal(x0 ^ x1);
            float val = fmaf(s_ts[i][d], n, s_tm[i][d]);
            s_pose[d * 512 + M0 + s] = val;
            out[OFF_SAMP + (size_t)((M0 + s) * BN + b) * 4 + d] = val;
        } else {
            int s = t - 384;
            uint32_t x0 = 0u, x1 = (uint32_t)(s * BN + b);
            tf2x32(keys.a2[i], keys.b2[i], x0, x1);
            float n = bits_to_normal(x0 ^ x1);
            float w = fmaf(s_rs[i], n, s_rm[i]);
            s_pose[3 * 512 + M0 + s] = w;
            out[OFF_SAMP + (size_t)((M0 + s) * BN + b) * 4 + 3] = w;
            float snv, csv;
            sincosf(w, &snv, &csv);
            s_cs[s] = csv; s_sn[s] = snv;
        }
        __syncthreads();

        // cost: 128 samples x 4 point-quarters; packed 2-points/instruction
        {
            const int s = t & 127, q = t >> 7;
            float tx = s_pose[0 * 512 + M0 + s];
            float ty = s_pose[1 * 512 + M0 + s];
            float tz = s_pose[2 * 512 + M0 + s];
            float cs = s_cs[s], sn = s_sn[s];
            ull cs2 = pk2(cs, cs), sn2 = pk2(sn, sn), nsn2 = pk2(-sn, -sn);
            ull tx2 = pk2(tx, tx), ty2 = pk2(ty, ty), tz2 = pk2(tz, tz);
            ull acc2 = 0ull;
            const ulonglong2* pv = reinterpret_cast<const ulonglong2*>(s_pts) + q * 64 * 4;
#pragma unroll 8
            for (int pp = 0; pp < 64; pp++)
                acc2 = pair_step(pv + pp * 4, cs2, sn2, nsn2, tx2, ty2, tz2, acc2);
            float al, ah; upk2(acc2, al, ah);
            red[t] = al + ah;
        }
        __syncthreads();
        if (t < 128) {
            float tot = (red[t] + red[t + 128]) + (red[t + 256] + red[t + 384]);
            s_cost[M0 + t] = 0.5f * tot;
        }
        __syncthreads();

        // logweights (mixture of i+1 proposals) + param update
        const int M = M0 + SI;
        float lwv = -1e30f;
        float px = 0.f, py = 0.f, pz = 0.f, pw = 0.f;
        if (t < M) {
            px = s_pose[0 * 512 + t]; py = s_pose[1 * 512 + t];
            pz = s_pose[2 * 512 + t]; pw = s_pose[3 * 512 + t];
            float mx = -1e30f;
            float lp[NI];
#pragma unroll 4
            for (int qq = 0; qq <= i; qq++) {
                float d0 = (px - s_tm[qq][0]) * s_its[qq][0];
                float d1 = (py - s_tm[qq][1]) * s_its[qq][1];
                float d2 = (pz - s_tm[qq][2]) * s_its[qq][2];
                float dr = (pw - s_rm[qq]) * s_irs[qq];
                float v = fmaf(-0.5f, fmaf(d0, d0, fmaf(d1, d1, fmaf(d2, d2, dr * dr))), s_cq[qq]);
                lp[qq] = v; mx = fmaxf(mx, v);
            }
            float se = 0.f;
#pragma unroll 4
            for (int qq = 0; qq <= i; qq++) se += expf(lp[qq] - mx);
            float mlp = mx + logf(se) - logf((float)(i + 1));
            lwv = -s_cost[t] - mlp;
            if (i == NI - 1) out[OFF_LW + (size_t)t * BN + b] = lwv;
        }
        __syncthreads();

        if (i < NI - 1) {
            float lmax = block_max(lwv, s_scr, t);
            float e = (t < M) ? expf(lwv - lmax) : 0.f;
            float vals[5] = { e, e * px, e * py, e * pz, e * pw };
            block_sum<5>(vals, s_scr, t);
            float inv = 1.0f / vals[0];
            float m0 = vals[1] * inv, m1 = vals[2] * inv, m2 = vals[3] * inv, m3 = vals[4] * inv;
            float vv[4] = { 0.f, 0.f, 0.f, 0.f };
            if (t < M) {
                float d;
                d = px - m0; vv[0] = e * d * d;
                d = py - m1; vv[1] = e * d * d;
                d = pz - m2; vv[2] = e * d * d;
                d = pw - m3; vv[3] = e * d * d;
            }
            block_sum<4>(vv, s_scr, t);
            if (t == 0) {
                s_tm[i + 1][0] = m0; s_tm[i + 1][1] = m1; s_tm[i + 1][2] = m2;
                float lsum = 0.f;
#pragma unroll
                for (int d = 0; d < 3; d++) {
                    float tsn = sqrtf(fmaf(vv[d], inv, 1e-5f));
                    s_ts[i + 1][d] = tsn;
                    s_its[i + 1][d] = 1.0f / tsn;
                    lsum += logf(tsn);
                }
                float rsn = sqrtf(fmaf(vv[3], inv, 1e-5f));
                s_rm[i + 1] = m3;
                s_rs[i + 1] = rsn;
                s_irs[i + 1] = 1.0f / rsn;
                s_cq[i + 1] = -(lsum + logf(rsn)) - 2.f * LOG2PI;
            }
            __syncthreads();
        }
    }
}

// ---------------- host ----------------
extern "C" void kernel_launch(void* const* d_in, const int* in_sizes, int n_in,
                              void* d_out, int out_size) {
    const float* x3d = (const float*)d_in[0];
    const float* x2d = (const float*)d_in[1];
    const float* w2d = (const float*)d_in[2];
    const float* cam = (const float*)d_in[3];
    const float* pose_init = (const float*)d_in[4];
    float* out = (float*)d_out;

    // key chain: key = jax.random.key(42); per iter: key,k1,k2 = split(key,3)
    Keys keys;
    uint32_t K0 = 0u, K1 = 42u;
    for (int i = 0; i < NI; i++) {
        uint32_t r[3][2];
        for (int j = 0; j < 3; j++) {
            uint32_t x0 = 0u, x1 = (uint32_t)j;
            tf2x32(K0, K1, x0, x1);
            r[j][0] = x0; r[j][1] = x1;
        }
        keys.a1[i] = r[1][0]; keys.b1[i] = r[1][1];
        keys.a2[i] = r[2][0]; keys.b2[i] = r[2][1];
        K0 = r[0][0]; K1 = r[0][1];
    }

    amis_kernel<<<BN, 512>>>(x3d, x2d, w2d, cam, pose_init, out, keys);
}